// round 7
// baseline (speedup 1.0000x reference)
#include <cuda_runtime.h>
#include <cuda_bf16.h>

// WaveletTransformLayer: x (128, 2048, 32) fp32 -> out (128, 32*8165) fp32
// Pyramid windows [2,4,8]; every output is a <=12-tap FIR along T per feature.
// Pure HBM-streaming kernel: read 33.5MB, write 133.8MB -> DRAM-bound.
// Design frozen pending first successful bench (7x broker timeouts so far).

#define B_N   128
#define T_LEN 2048
#define F_N   32
#define CHUNK 256
#define HALO  12
#define LDT   269   // odd pitch -> conflict-free smem transpose

// output region lengths per (b,f) series
#define L1 2047
#define L2 2044
#define L3 2037
#define OUT_PER_F (L1 + L2 + L3 + L3)   // 8165

__device__ __forceinline__ void fir12(const float* __restrict__ row,
                                      float& d1, float& d2, float& d3, float& a3) {
    float x0 = row[0],  x1 = row[1],  x2  = row[2],  x3  = row[3];
    float x4 = row[4],  x5 = row[5],  x6  = row[6],  x7  = row[7];
    float x8 = row[8],  x9 = row[9],  x10 = row[10], x11 = row[11];

    // level 1: MA2
    float a1 = 0.5f * (x0 + x1);
    d1 = x1 - a1;
    // level 2: MA4 of a1 == (x0 + 2(x1+x2+x3) + x4)/8
    float a2 = 0.125f * (x0 + 2.f * (x1 + x2 + x3) + x4);
    d2 = 0.5f * (x3 + x4) - a2;              // a1[t+3] - a2[t]
    // level 3: MA8 of a2 == composite kernel [1,3,5,7,8,8,8,8,7,5,3,1]/64
    a3 = (1.0f / 64.0f) *
         (x0 + 3.f * x1 + 5.f * x2 + 7.f * x3 +
          8.f * (x4 + x5 + x6 + x7) +
          7.f * x8 + 5.f * x9 + 3.f * x10 + x11);
    float a2_7 = 0.125f * (x7 + 2.f * (x8 + x9 + x10) + x11);  // a2[t+7]
    d3 = a2_7 - a3;
}

// streaming store: output is write-once data ~ L2 capacity -> evict-first
__device__ __forceinline__ void stcs(float* p, float v) {
    asm volatile("st.global.cs.f32 [%0], %1;" :: "l"(p), "f"(v) : "memory");
}

__global__ __launch_bounds__(256, 1)
void wavelet_kernel(const float* __restrict__ x, float* __restrict__ out) {
    __shared__ float s[F_N * LDT];

    const int b   = blockIdx.y;
    const int t0  = blockIdx.x * CHUNK;
    const int tid = threadIdx.x;

    // ---- load (CHUNK+HALO) x 32 tile, transposed into smem[f][t] ----
    // each T-row of x is 32 floats = 8 float4, 128B aligned -> LDG.128 coalesced.
    const float4* xb = reinterpret_cast<const float4*>(x + (size_t)b * T_LEN * F_N);
    #pragma unroll
    for (int i = tid; i < (CHUNK + HALO) * 8; i += 256) {
        int r  = i >> 3;      // local t
        int c  = i & 7;       // float4 slot within row
        int tg = t0 + r;
        float4 v = make_float4(0.f, 0.f, 0.f, 0.f);
        if (tg < T_LEN) v = xb[tg * 8 + c];
        int f = c * 4;
        s[(f + 0) * LDT + r] = v.x;
        s[(f + 1) * LDT + r] = v.y;
        s[(f + 2) * LDT + r] = v.z;
        s[(f + 3) * LDT + r] = v.w;
    }
    __syncthreads();

    const float invT = 1.0f / (float)T_LEN;
    const int   tg   = t0 + tid;                 // global t this thread produces
    float* outb = out + (size_t)b * F_N * OUT_PER_F;

    const bool v1 = (tg < L1);
    const bool v2 = (tg < L2);
    const bool v3 = (tg < L3);

    // process two features per iteration for ILP (two independent FIR chains)
    #pragma unroll 1
    for (int f = 0; f < F_N; f += 2) {
        float d1a, d2a, d3a, a3a;
        float d1b, d2b, d3b, a3b;
        fir12(s + (f + 0) * LDT + tid, d1a, d2a, d3a, a3a);
        fir12(s + (f + 1) * LDT + tid, d1b, d2b, d3b, a3b);

        float* ofa = outb + (f + 0) * OUT_PER_F;
        float* ofb = outb + (f + 1) * OUT_PER_F;
        if (v1) { stcs(ofa + tg, d1a * invT);           stcs(ofb + tg, d1b * invT); }
        if (v2) { stcs(ofa + L1 + tg, d2a * invT);      stcs(ofb + L1 + tg, d2b * invT); }
        if (v3) {
            stcs(ofa + L1 + L2 + tg,      d3a * invT);  stcs(ofb + L1 + L2 + tg,      d3b * invT);
            stcs(ofa + L1 + L2 + L3 + tg, a3a * invT);  stcs(ofb + L1 + L2 + L3 + tg, a3b * invT);
        }
    }
}

extern "C" void kernel_launch(void* const* d_in, const int* in_sizes, int n_in,
                              void* d_out, int out_size) {
    const float* x = (const float*)d_in[0];
    float* out = (float*)d_out;
    dim3 grid(T_LEN / CHUNK, B_N);   // (8, 128)
    wavelet_kernel<<<grid, 256>>>(x, out);
}